// round 1
// baseline (speedup 1.0000x reference)
#include <cuda_runtime.h>

#define NATOMS 25000
#define MNBR 32
#define DIM 128

// Scratch (device globals: allocation-free per harness rules)
__device__ float g_A[(size_t)NATOMS * DIM];    // X @ W1_top + b1
__device__ float g_B[(size_t)NATOMS * DIM];    // X @ W1_bot
__device__ float g_H[(size_t)NATOMS * DIM];    // sum_j relu(A_i + B_j)
__device__ float g_agg[(size_t)NATOMS * DIM];  // H @ msg_W2 + 32*b2
__device__ float g_u[(size_t)NATOMS * DIM];    // relu([X,agg] @ upd_W1 + b1)

// ---------------------------------------------------------------------------
// Generic fp32 GEMM: C = epi( A1 @ W1 [+ A2 @ W2] + bias*bscale [+ res] )
// A: M x 128 row-major, W: 128 x 128 row-major, C: M x 128.
// Block tile 128x128, 256 threads, 8x8 register tile per thread.
// ---------------------------------------------------------------------------
template<bool HAS2, bool RELU, bool HASRES>
__global__ __launch_bounds__(256, 2)
void gemm128_kernel(const float* __restrict__ A1, const float* __restrict__ W1,
                    const float* __restrict__ A2, const float* __restrict__ W2,
                    const float* __restrict__ bias, float bscale,
                    const float* __restrict__ res,
                    float* __restrict__ C, int M)
{
    __shared__ float Ast[16][132];  // transposed A tile [k][m], padded
    __shared__ float Ws[16][128];   // W tile [k][n]

    const int tid = threadIdx.x;
    const int tx = tid & 15;        // 16 col-groups
    const int ty = tid >> 4;        // 16 row-groups
    const int m0 = blockIdx.x * 128;
    const int r0 = ty * 8;
    const int c0 = tx * 8;

    float acc[8][8];
#pragma unroll
    for (int i = 0; i < 8; ++i)
#pragma unroll
        for (int j = 0; j < 8; ++j) acc[i][j] = 0.f;

    const int nphase = HAS2 ? 2 : 1;
    for (int p = 0; p < nphase; ++p) {
        const float* Ag = (HAS2 && p) ? A2 : A1;
        const float* Wg = (HAS2 && p) ? W2 : W1;
        for (int k0 = 0; k0 < DIM; k0 += 16) {
            // global -> regs
            float4 av[2], wv[2];
#pragma unroll
            for (int i = 0; i < 2; ++i) {
                int t = tid + i * 256;
                int row = t >> 2;
                int c4 = (t & 3) << 2;
                int gr = m0 + row;
                if (gr >= M) gr = M - 1;  // clamp; stores are guarded
                av[i] = *reinterpret_cast<const float4*>(Ag + (size_t)gr * DIM + k0 + c4);
                int wr = t >> 5;
                int wc = (t & 31) << 2;
                wv[i] = *reinterpret_cast<const float4*>(Wg + (size_t)(k0 + wr) * DIM + wc);
            }
            __syncthreads();  // previous tile fully consumed
            // regs -> smem (A transposed)
#pragma unroll
            for (int i = 0; i < 2; ++i) {
                int t = tid + i * 256;
                int row = t >> 2;
                int c4 = (t & 3) << 2;
                Ast[c4 + 0][row] = av[i].x;
                Ast[c4 + 1][row] = av[i].y;
                Ast[c4 + 2][row] = av[i].z;
                Ast[c4 + 3][row] = av[i].w;
                int wr = t >> 5;
                int wc = (t & 31) << 2;
                *reinterpret_cast<float4*>(&Ws[wr][wc]) = wv[i];
            }
            __syncthreads();
            // compute
#pragma unroll
            for (int kk = 0; kk < 16; ++kk) {
                float a[8], w[8];
                *reinterpret_cast<float4*>(&a[0]) = *reinterpret_cast<const float4*>(&Ast[kk][r0]);
                *reinterpret_cast<float4*>(&a[4]) = *reinterpret_cast<const float4*>(&Ast[kk][r0 + 4]);
                *reinterpret_cast<float4*>(&w[0]) = *reinterpret_cast<const float4*>(&Ws[kk][c0]);
                *reinterpret_cast<float4*>(&w[4]) = *reinterpret_cast<const float4*>(&Ws[kk][c0 + 4]);
#pragma unroll
                for (int i = 0; i < 8; ++i)
#pragma unroll
                    for (int j = 0; j < 8; ++j)
                        acc[i][j] = fmaf(a[i], w[j], acc[i][j]);
            }
        }
    }

    // epilogue
    float bv[8];
#pragma unroll
    for (int j = 0; j < 8; ++j) bv[j] = bias ? bias[c0 + j] * bscale : 0.f;

#pragma unroll
    for (int i = 0; i < 8; ++i) {
        int gr = m0 + r0 + i;
        if (gr < M) {
            float v[8];
#pragma unroll
            for (int j = 0; j < 8; ++j) v[j] = acc[i][j] + bv[j];
            if (HASRES) {
                float4 rv0 = *reinterpret_cast<const float4*>(res + (size_t)gr * DIM + c0);
                float4 rv1 = *reinterpret_cast<const float4*>(res + (size_t)gr * DIM + c0 + 4);
                v[0] += rv0.x; v[1] += rv0.y; v[2] += rv0.z; v[3] += rv0.w;
                v[4] += rv1.x; v[5] += rv1.y; v[6] += rv1.z; v[7] += rv1.w;
            }
            if (RELU) {
#pragma unroll
                for (int j = 0; j < 8; ++j) v[j] = fmaxf(v[j], 0.f);
            }
            *reinterpret_cast<float4*>(C + (size_t)gr * DIM + c0) =
                make_float4(v[0], v[1], v[2], v[3]);
            *reinterpret_cast<float4*>(C + (size_t)gr * DIM + c0 + 4) =
                make_float4(v[4], v[5], v[6], v[7]);
        }
    }
}

// ---------------------------------------------------------------------------
// Gather + edge ReLU + neighbor-sum: H[i] = sum_m relu(A[i] + B[nbr[i][m]])
// One warp per node; lane owns dims [4*lane, 4*lane+4).
// Handles nbr_indices as int32 OR int64 (runtime warp-ballot detection).
// ---------------------------------------------------------------------------
__global__ __launch_bounds__(256)
void gather_sum_kernel(const float* __restrict__ A,
                       const float* __restrict__ B,
                       const void* __restrict__ idx_raw,
                       float* __restrict__ H, int M)
{
    int node = blockIdx.x * 8 + (threadIdx.x >> 5);
    int lane = threadIdx.x & 31;
    if (node >= M) return;

    // dtype detection: if indices are int64 (little-endian, values < 2^31),
    // every odd 32-bit word of the buffer is zero.
    const int* idx32 = (const int*)idx_raw;
    int w = idx32[(size_t)node * 32 + lane];
    unsigned zmask = __ballot_sync(0xffffffffu, w == 0);
    int j;
    if ((zmask & 0xAAAAAAAAu) == 0xAAAAAAAAu) {
        long long jv = ((const long long*)idx_raw)[(size_t)node * 32 + lane];
        j = (int)jv;
    } else {
        j = w;
    }

    float4 a = reinterpret_cast<const float4*>(A + (size_t)node * DIM)[lane];
    float4 acc = make_float4(0.f, 0.f, 0.f, 0.f);
#pragma unroll
    for (int m = 0; m < 32; ++m) {
        int jm = __shfl_sync(0xffffffffu, j, m);
        float4 b = __ldg(reinterpret_cast<const float4*>(B + (size_t)jm * DIM) + lane);
        acc.x += fmaxf(a.x + b.x, 0.f);
        acc.y += fmaxf(a.y + b.y, 0.f);
        acc.z += fmaxf(a.z + b.z, 0.f);
        acc.w += fmaxf(a.w + b.w, 0.f);
    }
    reinterpret_cast<float4*>(H + (size_t)node * DIM)[lane] = acc;
}

// ---------------------------------------------------------------------------
// Inputs (metadata order):
//  0 atom_features [25000,128] f32
//  1 nbr_features  [25000,32,128] f32 (UNUSED)
//  2 nbr_indices   [25000,32] int (32- or 64-bit, auto-detected)
//  3 msg_W1 [256,128]  4 msg_b1 [128]  5 msg_W2 [128,128]  6 msg_b2 [128]
//  7 upd_W1 [256,128]  8 upd_b1 [128]  9 upd_W2 [128,128] 10 upd_b2 [128]
// ---------------------------------------------------------------------------
extern "C" void kernel_launch(void* const* d_in, const int* in_sizes, int n_in,
                              void* d_out, int out_size)
{
    const float* X     = (const float*)d_in[0];
    const void*  idx   = d_in[2];
    const float* msgW1 = (const float*)d_in[3];
    const float* msgb1 = (const float*)d_in[4];
    const float* msgW2 = (const float*)d_in[5];
    const float* msgb2 = (const float*)d_in[6];
    const float* updW1 = (const float*)d_in[7];
    const float* updb1 = (const float*)d_in[8];
    const float* updW2 = (const float*)d_in[9];
    const float* updb2 = (const float*)d_in[10];
    float* out = (float*)d_out;

    float *A, *B, *H, *agg, *u;
    cudaGetSymbolAddress((void**)&A,   g_A);
    cudaGetSymbolAddress((void**)&B,   g_B);
    cudaGetSymbolAddress((void**)&H,   g_H);
    cudaGetSymbolAddress((void**)&agg, g_agg);
    cudaGetSymbolAddress((void**)&u,   g_u);

    const int M = NATOMS;
    dim3 gblk((M + 127) / 128);

    // A = X @ W1_top + b1 ; B = X @ W1_bot
    gemm128_kernel<false, false, false><<<gblk, 256>>>(
        X, msgW1, nullptr, nullptr, msgb1, 1.f, nullptr, A, M);
    gemm128_kernel<false, false, false><<<gblk, 256>>>(
        X, msgW1 + DIM * DIM, nullptr, nullptr, nullptr, 0.f, nullptr, B, M);

    // H[i] = sum_j relu(A[i] + B[j])
    gather_sum_kernel<<<(M + 7) / 8, 256>>>(A, B, idx, H, M);

    // agg = H @ msg_W2 + 32*b2
    gemm128_kernel<false, false, false><<<gblk, 256>>>(
        H, msgW2, nullptr, nullptr, msgb2, (float)MNBR, nullptr, agg, M);

    // u = relu(X @ updW1_top + agg @ updW1_bot + upd_b1)
    gemm128_kernel<true, true, false><<<gblk, 256>>>(
        X, updW1, agg, updW1 + DIM * DIM, updb1, 1.f, nullptr, u, M);

    // out = relu(X + u @ updW2 + upd_b2)
    gemm128_kernel<false, true, true><<<gblk, 256>>>(
        u, updW2, nullptr, nullptr, updb2, 1.f, X, out, M);

    (void)in_sizes; (void)n_in; (void)out_size;
}

// round 2
// speedup vs baseline: 1.0129x; 1.0129x over previous
#include <cuda_runtime.h>

#define NATOMS 25000
#define MNBR 32
#define DIM 128

// Scratch (device globals: allocation-free per harness rules)
__device__ float g_A[(size_t)NATOMS * DIM];    // X @ W1_top + b1
__device__ float g_B[(size_t)NATOMS * DIM];    // X @ W1_bot
__device__ float g_H[(size_t)NATOMS * DIM];    // sum_j relu(A_i + B_j)
__device__ float g_agg[(size_t)NATOMS * DIM];  // H @ msg_W2 + 32*b2
__device__ float g_u[(size_t)NATOMS * DIM];    // relu([X,agg] @ upd_W1 + b1)

// ---------------------------------------------------------------------------
// fp32 GEMM using packed fma.rn.f32x2 (Blackwell FFMA2, 2x scalar FFMA rate).
// C = epi( A1 @ W1 [+ A2 @ W2] + bias*bscale [+ res] )
// A: M x 128 row-major, W: 128 x 128 row-major, C: M x 128.
// Block tile 128x128, 256 threads, 8x8 register tile per thread
// (accumulators held as 8x4 packed f32x2 pairs).
// ---------------------------------------------------------------------------
template<bool HAS2, bool RELU, bool HASRES>
__global__ __launch_bounds__(256, 2)
void gemm128_kernel(const float* __restrict__ A1, const float* __restrict__ W1,
                    const float* __restrict__ A2, const float* __restrict__ W2,
                    const float* __restrict__ bias, float bscale,
                    const float* __restrict__ res,
                    float* __restrict__ C, int M)
{
    __shared__ float Ast[16][132];  // transposed A tile [k][m], padded
    __shared__ float Ws[16][128];   // W tile [k][n]

    const int tid = threadIdx.x;
    const int tx = tid & 15;        // 16 col-groups
    const int ty = tid >> 4;        // 16 row-groups
    const int m0 = blockIdx.x * 128;
    const int r0 = ty * 8;
    const int c0 = tx * 8;

    // packed accumulators: acc[i][j] holds cols (c0+2j, c0+2j+1) of row r0+i
    unsigned long long acc[8][4];
#pragma unroll
    for (int i = 0; i < 8; ++i)
#pragma unroll
        for (int j = 0; j < 4; ++j) acc[i][j] = 0ull;

    const int T = HAS2 ? 16 : 8;    // 16-wide K tiles (x2 phases when HAS2)
    float4 av[2], wv[2];

    auto load_tile = [&](int t) {
        const float* Ag = (HAS2 && (t & 8)) ? A2 : A1;
        const float* Wg = (HAS2 && (t & 8)) ? W2 : W1;
        const int k0 = (t & 7) << 4;
#pragma unroll
        for (int i = 0; i < 2; ++i) {
            int tt = tid + i * 256;
            int row = tt >> 2;
            int c4 = (tt & 3) << 2;
            int gr = m0 + row;
            if (gr >= M) gr = M - 1;  // clamp; stores are guarded
            av[i] = *reinterpret_cast<const float4*>(Ag + (size_t)gr * DIM + k0 + c4);
            int wr = tt >> 5;
            int wc = (tt & 31) << 2;
            wv[i] = *reinterpret_cast<const float4*>(Wg + (size_t)(k0 + wr) * DIM + wc);
        }
    };

    load_tile(0);

    for (int t = 0; t < T; ++t) {
        __syncthreads();  // previous tile fully consumed
#pragma unroll
        for (int i = 0; i < 2; ++i) {
            int tt = tid + i * 256;
            int row = tt >> 2;
            int c4 = (tt & 3) << 2;
            Ast[c4 + 0][row] = av[i].x;
            Ast[c4 + 1][row] = av[i].y;
            Ast[c4 + 2][row] = av[i].z;
            Ast[c4 + 3][row] = av[i].w;
            int wr = tt >> 5;
            int wc = (tt & 31) << 2;
            *reinterpret_cast<float4*>(&Ws[wr][wc]) = wv[i];
        }
        __syncthreads();
        if (t + 1 < T) load_tile(t + 1);  // prefetch next tile into regs

#pragma unroll
        for (int kk = 0; kk < 16; ++kk) {
            float a[8];
            *reinterpret_cast<float4*>(&a[0]) = *reinterpret_cast<const float4*>(&Ast[kk][r0]);
            *reinterpret_cast<float4*>(&a[4]) = *reinterpret_cast<const float4*>(&Ast[kk][r0 + 4]);
            unsigned long long w[4];
            {
                ulonglong2 wq0 = *reinterpret_cast<const ulonglong2*>(&Ws[kk][c0]);
                ulonglong2 wq1 = *reinterpret_cast<const ulonglong2*>(&Ws[kk][c0 + 4]);
                w[0] = wq0.x; w[1] = wq0.y; w[2] = wq1.x; w[3] = wq1.y;
            }
#pragma unroll
            for (int i = 0; i < 8; ++i) {
                unsigned ai = __float_as_uint(a[i]);
                unsigned long long ap;
                asm("mov.b64 %0, {%1, %1};" : "=l"(ap) : "r"(ai));
#pragma unroll
                for (int j = 0; j < 4; ++j)
                    asm("fma.rn.f32x2 %0, %1, %2, %0;"
                        : "+l"(acc[i][j]) : "l"(ap), "l"(w[j]));
            }
        }
    }

    // epilogue
    float bv[8];
#pragma unroll
    for (int j = 0; j < 8; ++j) bv[j] = bias ? bias[c0 + j] * bscale : 0.f;

#pragma unroll
    for (int i = 0; i < 8; ++i) {
        int gr = m0 + r0 + i;
        if (gr < M) {
            float v[8];
#pragma unroll
            for (int j = 0; j < 4; ++j) {
                unsigned lo, hi;
                asm("mov.b64 {%0, %1}, %2;" : "=r"(lo), "=r"(hi) : "l"(acc[i][j]));
                v[2 * j]     = __uint_as_float(lo) + bv[2 * j];
                v[2 * j + 1] = __uint_as_float(hi) + bv[2 * j + 1];
            }
            if (HASRES) {
                float4 rv0 = *reinterpret_cast<const float4*>(res + (size_t)gr * DIM + c0);
                float4 rv1 = *reinterpret_cast<const float4*>(res + (size_t)gr * DIM + c0 + 4);
                v[0] += rv0.x; v[1] += rv0.y; v[2] += rv0.z; v[3] += rv0.w;
                v[4] += rv1.x; v[5] += rv1.y; v[6] += rv1.z; v[7] += rv1.w;
            }
            if (RELU) {
#pragma unroll
                for (int j = 0; j < 8; ++j) v[j] = fmaxf(v[j], 0.f);
            }
            *reinterpret_cast<float4*>(C + (size_t)gr * DIM + c0) =
                make_float4(v[0], v[1], v[2], v[3]);
            *reinterpret_cast<float4*>(C + (size_t)gr * DIM + c0 + 4) =
                make_float4(v[4], v[5], v[6], v[7]);
        }
    }
}

// ---------------------------------------------------------------------------
// Gather + edge ReLU + neighbor-sum: H[i] = sum_m relu(A[i] + B[nbr[i][m]])
// One warp per node; lane owns dims [4*lane, 4*lane+4).
// Handles nbr_indices as int32 OR int64 (runtime warp-ballot detection).
// ---------------------------------------------------------------------------
__global__ __launch_bounds__(256)
void gather_sum_kernel(const float* __restrict__ A,
                       const float* __restrict__ B,
                       const void* __restrict__ idx_raw,
                       float* __restrict__ H, int M)
{
    int node = blockIdx.x * 8 + (threadIdx.x >> 5);
    int lane = threadIdx.x & 31;
    if (node >= M) return;

    // dtype detection: if indices are int64 (little-endian, values < 2^31),
    // every odd 32-bit word of the buffer is zero.
    const int* idx32 = (const int*)idx_raw;
    int w = idx32[(size_t)node * 32 + lane];
    unsigned zmask = __ballot_sync(0xffffffffu, w == 0);
    int j;
    if ((zmask & 0xAAAAAAAAu) == 0xAAAAAAAAu) {
        long long jv = ((const long long*)idx_raw)[(size_t)node * 32 + lane];
        j = (int)jv;
    } else {
        j = w;
    }

    float4 a = reinterpret_cast<const float4*>(A + (size_t)node * DIM)[lane];
    float4 acc = make_float4(0.f, 0.f, 0.f, 0.f);
#pragma unroll
    for (int m = 0; m < 32; ++m) {
        int jm = __shfl_sync(0xffffffffu, j, m);
        float4 b = __ldg(reinterpret_cast<const float4*>(B + (size_t)jm * DIM) + lane);
        acc.x += fmaxf(a.x + b.x, 0.f);
        acc.y += fmaxf(a.y + b.y, 0.f);
        acc.z += fmaxf(a.z + b.z, 0.f);
        acc.w += fmaxf(a.w + b.w, 0.f);
    }
    reinterpret_cast<float4*>(H + (size_t)node * DIM)[lane] = acc;
}

// ---------------------------------------------------------------------------
// Inputs (metadata order):
//  0 atom_features [25000,128] f32
//  1 nbr_features  [25000,32,128] f32 (UNUSED)
//  2 nbr_indices   [25000,32] int (32- or 64-bit, auto-detected)
//  3 msg_W1 [256,128]  4 msg_b1 [128]  5 msg_W2 [128,128]  6 msg_b2 [128]
//  7 upd_W1 [256,128]  8 upd_b1 [128]  9 upd_W2 [128,128] 10 upd_b2 [128]
// ---------------------------------------------------------------------------
extern "C" void kernel_launch(void* const* d_in, const int* in_sizes, int n_in,
                              void* d_out, int out_size)
{
    const float* X     = (const float*)d_in[0];
    const void*  idx   = d_in[2];
    const float* msgW1 = (const float*)d_in[3];
    const float* msgb1 = (const float*)d_in[4];
    const float* msgW2 = (const float*)d_in[5];
    const float* msgb2 = (const float*)d_in[6];
    const float* updW1 = (const float*)d_in[7];
    const float* updb1 = (const float*)d_in[8];
    const float* updW2 = (const float*)d_in[9];
    const float* updb2 = (const float*)d_in[10];
    float* out = (float*)d_out;

    float *A, *B, *H, *agg, *u;
    cudaGetSymbolAddress((void**)&A,   g_A);
    cudaGetSymbolAddress((void**)&B,   g_B);
    cudaGetSymbolAddress((void**)&H,   g_H);
    cudaGetSymbolAddress((void**)&agg, g_agg);
    cudaGetSymbolAddress((void**)&u,   g_u);

    const int M = NATOMS;
    dim3 gblk((M + 127) / 128);

    // A = X @ W1_top + b1 ; B = X @ W1_bot
    gemm128_kernel<false, false, false><<<gblk, 256>>>(
        X, msgW1, nullptr, nullptr, msgb1, 1.f, nullptr, A, M);
    gemm128_kernel<false, false, false><<<gblk, 256>>>(
        X, msgW1 + DIM * DIM, nullptr, nullptr, nullptr, 0.f, nullptr, B, M);

    // H[i] = sum_j relu(A[i] + B[j])
    gather_sum_kernel<<<(M + 7) / 8, 256>>>(A, B, idx, H, M);

    // agg = H @ msg_W2 + 32*b2
    gemm128_kernel<false, false, false><<<gblk, 256>>>(
        H, msgW2, nullptr, nullptr, msgb2, (float)MNBR, nullptr, agg, M);

    // u = relu(X @ updW1_top + agg @ updW1_bot + upd_b1)
    gemm128_kernel<true, true, false><<<gblk, 256>>>(
        X, updW1, agg, updW1 + DIM * DIM, updb1, 1.f, nullptr, u, M);

    // out = relu(X + u @ updW2 + upd_b2)
    gemm128_kernel<false, true, true><<<gblk, 256>>>(
        u, updW2, nullptr, nullptr, updb2, 1.f, X, out, M);

    (void)in_sizes; (void)n_in; (void)out_size;
}

// round 4
// speedup vs baseline: 1.6205x; 1.5999x over previous
#include <cuda_runtime.h>
#include <cuda_bf16.h>
#include <cstdint>

#define NATOMS 25000
#define MNBR 32
#define DIM 128
#define MGRID 196   // ceil(25000/128)

// ---------------- scratch (device globals) ----------------
__device__ float g_A[(size_t)NATOMS * DIM];
__device__ float g_B[(size_t)NATOMS * DIM];
__device__ __nv_bfloat16 g_Xh[(size_t)NATOMS * DIM], g_Xl[(size_t)NATOMS * DIM];
__device__ __nv_bfloat16 g_Hh[(size_t)NATOMS * DIM], g_Hl[(size_t)NATOMS * DIM];
__device__ __nv_bfloat16 g_aggh[(size_t)NATOMS * DIM], g_aggl[(size_t)NATOMS * DIM];
__device__ __nv_bfloat16 g_uh[(size_t)NATOMS * DIM], g_ul[(size_t)NATOMS * DIM];
// transposed + k-permuted bf16-split weights: Wt[n][k'], k' permuted within 16-chunks
__device__ __nv_bfloat16 g_w1h[256 * 128], g_w1l[256 * 128];   // [W1top^T | W1bot^T]
__device__ __nv_bfloat16 g_w2h[128 * 128], g_w2l[128 * 128];   // msgW2^T
__device__ __nv_bfloat16 g_u1h[128 * 256], g_u1l[128 * 256];   // updW1^T (N=128,K=256)
__device__ __nv_bfloat16 g_u2h[128 * 128], g_u2l[128 * 128];   // updW2^T

// ---------------- helpers ----------------
__device__ __forceinline__ uint32_t smem_u32(const void* p) {
    uint32_t a;
    asm("{ .reg .u64 t; cvta.to.shared.u64 t, %1; cvt.u32.u64 %0, t; }" : "=r"(a) : "l"(p));
    return a;
}
__device__ __forceinline__ void ldmat_x4(uint32_t* r, uint32_t a) {
    asm volatile("ldmatrix.sync.aligned.m8n8.x4.shared.b16 {%0,%1,%2,%3}, [%4];"
        : "=r"(r[0]), "=r"(r[1]), "=r"(r[2]), "=r"(r[3]) : "r"(a));
}
__device__ __forceinline__ void hmma(float* d, const uint32_t* a, uint2 b) {
    asm volatile("mma.sync.aligned.m16n8k16.row.col.f32.bf16.bf16.f32 "
        "{%0,%1,%2,%3}, {%4,%5,%6,%7}, {%8,%9}, {%0,%1,%2,%3};"
        : "+f"(d[0]), "+f"(d[1]), "+f"(d[2]), "+f"(d[3])
        : "r"(a[0]), "r"(a[1]), "r"(a[2]), "r"(a[3]), "r"(b.x), "r"(b.y));
}

// ---------------- conversion kernels ----------------
__global__ void conv_x_kernel(const float* __restrict__ X,
                              __nv_bfloat16* __restrict__ Xh,
                              __nv_bfloat16* __restrict__ Xl, int n4) {
    int i = blockIdx.x * 256 + threadIdx.x;
    if (i >= n4) return;
    float4 f = reinterpret_cast<const float4*>(X)[i];
    float v[4] = {f.x, f.y, f.z, f.w};
    unsigned long long ph = 0, pl = 0;
#pragma unroll
    for (int e = 0; e < 4; ++e) {
        __nv_bfloat16 h = __float2bfloat16(v[e]);
        __nv_bfloat16 l = __float2bfloat16(v[e] - __bfloat162float(h));
        ph |= (unsigned long long)__bfloat16_as_ushort(h) << (16 * e);
        pl |= (unsigned long long)__bfloat16_as_ushort(l) << (16 * e);
    }
    reinterpret_cast<unsigned long long*>(Xh)[i] = ph;
    reinterpret_cast<unsigned long long*>(Xl)[i] = pl;
}

// within-16 k-permutation so a B fragment (k: 2tg,2tg+1,2tg+8,2tg+9) is one LDS.64
__device__ __forceinline__ int kperm(int kdst) {
    int o = kdst & 15;
    int src = (o >> 2) * 2 + (o & 1) + ((o & 2) ? 8 : 0);
    return (kdst & ~15) + src;
}

__global__ void conv_w_kernel(const float* __restrict__ msgW1,
                              const float* __restrict__ msgW2,
                              const float* __restrict__ updW1,
                              const float* __restrict__ updW2,
                              __nv_bfloat16* __restrict__ w1h, __nv_bfloat16* __restrict__ w1l,
                              __nv_bfloat16* __restrict__ w2h, __nv_bfloat16* __restrict__ w2l,
                              __nv_bfloat16* __restrict__ u1h, __nv_bfloat16* __restrict__ u1l,
                              __nv_bfloat16* __restrict__ u2h, __nv_bfloat16* __restrict__ u2l) {
    int idx = blockIdx.x * 256 + threadIdx.x;
    float v; __nv_bfloat16 *ph, *pl; int off;
    if (idx < 32768) {                       // w1: [256 n][128 k]
        int n = idx >> 7, ks = kperm(idx & 127);
        v = (n < 128) ? msgW1[ks * 128 + n] : msgW1[(128 + ks) * 128 + (n - 128)];
        ph = w1h; pl = w1l; off = idx;
    } else if (idx < 49152) {                // w2: [128][128]
        int i = idx - 32768; int n = i >> 7, ks = kperm(i & 127);
        v = msgW2[ks * 128 + n]; ph = w2h; pl = w2l; off = i;
    } else if (idx < 81920) {                // u1: [128 n][256 k]
        int i = idx - 49152; int n = i >> 8, ks = kperm(i & 255);
        v = updW1[ks * 128 + n]; ph = u1h; pl = u1l; off = i;
    } else if (idx < 98304) {                // u2: [128][128]
        int i = idx - 81920; int n = i >> 7, ks = kperm(i & 127);
        v = updW2[ks * 128 + n]; ph = u2h; pl = u2l; off = i;
    } else return;
    __nv_bfloat16 h = __float2bfloat16(v);
    ph[off] = h;
    pl[off] = __float2bfloat16(v - __bfloat162float(h));
}

// ---------------- smem tile loaders ----------------
// A tile: 128 rows x 128 bf16, smem row stride 272B (136 bf16)
__device__ __forceinline__ void load_a_tile(char* sm, int off,
                                            const __nv_bfloat16* __restrict__ src,
                                            int m0, int M) {
    int tid = threadIdx.x;
#pragma unroll
    for (int q = 0; q < 8; ++q) {
        int s = tid + q * 256;
        int r = s >> 4, c8 = (s & 15) << 3;
        int gr = m0 + r; if (gr >= M) gr = M - 1;
        uint4 v = *reinterpret_cast<const uint4*>(src + (size_t)gr * DIM + c8);
        *reinterpret_cast<uint4*>(sm + off + r * 272 + (c8 << 1)) = v;
    }
}
// W tile: 128 rows(n) x 128 bf16(k'), smem row stride 288B (144 bf16)
__device__ __forceinline__ void load_w_tile(char* sm, int off,
                                            const __nv_bfloat16* __restrict__ src,
                                            int n0, int kstride, int k0) {
    int tid = threadIdx.x;
#pragma unroll
    for (int q = 0; q < 8; ++q) {
        int s = tid + q * 256;
        int r = s >> 4, c8 = (s & 15) << 3;
        uint4 v = *reinterpret_cast<const uint4*>(src + (size_t)(n0 + r) * kstride + k0 + c8);
        *reinterpret_cast<uint4*>(sm + off + r * 288 + (c8 << 1)) = v;
    }
}

// ---------------- HMMA GEMM kernel ----------------
// MODE 0: [A|B] = X @ [W1top|W1bot] (2 N-passes; pass0 +b1) -> f32
// MODE 1: agg = H @ msgW2 + 32*b2 -> bf16 hi/lo
// MODE 2: u = relu([X,agg] @ updW1 + b1) (K=256, 2 K-phases) -> bf16 hi/lo
// MODE 3: out = relu(X + u @ updW2 + b2) -> f32
template<int MODE>
__global__ __launch_bounds__(256, 1)
void mma_kernel(const __nv_bfloat16* __restrict__ A1h, const __nv_bfloat16* __restrict__ A1l,
                const __nv_bfloat16* __restrict__ A2h, const __nv_bfloat16* __restrict__ A2l,
                const __nv_bfloat16* __restrict__ Wh,  const __nv_bfloat16* __restrict__ Wl,
                const float* __restrict__ bias, float bscale,
                const float* __restrict__ resid,
                float* __restrict__ outf, float* __restrict__ outf2,
                __nv_bfloat16* __restrict__ obh, __nv_bfloat16* __restrict__ obl,
                int M)
{
    constexpr int KH = (MODE == 2) ? 2 : 1;   // K phases
    constexpr int NP = (MODE == 0) ? 2 : 1;   // N passes
    constexpr int OFF_AH = 0;
    constexpr int OFF_AL = 34816;             // 128*272
    constexpr int OFF_WH = 69632;
    constexpr int OFF_WL = 69632 + 36864;     // 128*288

    extern __shared__ char smem[];
    const uint32_t smb = smem_u32(smem);
    const int tid = threadIdx.x, wid = tid >> 5, lane = tid & 31;
    const int g = lane >> 2, tg = lane & 3;
    const int m0 = blockIdx.x * 128;
    const int m0w = (wid & 3) * 32, n0w = (wid >> 2) * 64;
    const int kw = KH * 128;                  // W gmem k-stride

    for (int p = 0; p < NP; ++p) {
        float d[2][8][4];
#pragma unroll
        for (int i = 0; i < 2; ++i)
#pragma unroll
            for (int j = 0; j < 8; ++j)
#pragma unroll
                for (int e = 0; e < 4; ++e) d[i][j][e] = 0.f;

        for (int kh = 0; kh < KH; ++kh) {
            __syncthreads();  // previous phase/pass fully consumed smem
            if (p == 0) {
                load_a_tile(smem, OFF_AH, kh ? A2h : A1h, m0, M);
                load_a_tile(smem, OFF_AL, kh ? A2l : A1l, m0, M);
            }
            load_w_tile(smem, OFF_WH, Wh, p * 128, kw, kh * 128);
            load_w_tile(smem, OFF_WL, Wl, p * 128, kw, kh * 128);
            __syncthreads();

            for (int k0 = 0; k0 < 128; k0 += 16) {
                uint32_t ah[2][4], al[2][4];
#pragma unroll
                for (int i = 0; i < 2; ++i) {
                    uint32_t ra = (uint32_t)((m0w + i * 16 + (lane & 15)) * 272 +
                                             ((k0 + ((lane >> 4) << 3)) << 1));
                    ldmat_x4(ah[i], smb + OFF_AH + ra);
                    ldmat_x4(al[i], smb + OFF_AL + ra);
                }
#pragma unroll
                for (int j = 0; j < 8; ++j) {
                    int woff = (n0w + j * 8 + g) * 288 + (k0 << 1) + (tg << 3);
                    uint2 bh = *reinterpret_cast<const uint2*>(smem + OFF_WH + woff);
                    uint2 bl = *reinterpret_cast<const uint2*>(smem + OFF_WL + woff);
#pragma unroll
                    for (int i = 0; i < 2; ++i) {
                        hmma(d[i][j], ah[i], bh);
                        hmma(d[i][j], ah[i], bl);
                        hmma(d[i][j], al[i], bh);
                    }
                }
            }
        }

        // ---- epilogue for pass p ----
#pragma unroll
        for (int j = 0; j < 8; ++j) {
            int c = n0w + j * 8 + 2 * tg;
            float b0 = 0.f, b1 = 0.f;
            if (!(MODE == 0 && p == 1)) {
                b0 = bscale * __ldg(bias + c);
                b1 = bscale * __ldg(bias + c + 1);
            }
#pragma unroll
            for (int i = 0; i < 2; ++i) {
#pragma unroll
                for (int h = 0; h < 2; ++h) {
                    int m = m0 + m0w + i * 16 + g + h * 8;
                    if (m >= M) continue;
                    float v0 = d[i][j][2 * h] + b0;
                    float v1 = d[i][j][2 * h + 1] + b1;
                    if (MODE == 0) {
                        float* dst = p ? outf2 : outf;
                        *reinterpret_cast<float2*>(dst + (size_t)m * DIM + c) =
                            make_float2(v0, v1);
                    } else if (MODE == 3) {
                        float2 rx = *reinterpret_cast<const float2*>(resid + (size_t)m * DIM + c);
                        v0 = fmaxf(v0 + rx.x, 0.f);
                        v1 = fmaxf(v1 + rx.y, 0.f);
                        *reinterpret_cast<float2*>(outf + (size_t)m * DIM + c) =
                            make_float2(v0, v1);
                    } else {
                        if (MODE == 2) { v0 = fmaxf(v0, 0.f); v1 = fmaxf(v1, 0.f); }
                        __nv_bfloat16 h0 = __float2bfloat16(v0), h1 = __float2bfloat16(v1);
                        float l0 = v0 - __bfloat162float(h0);
                        float l1 = v1 - __bfloat162float(h1);
                        uint32_t hh = ((uint32_t)__bfloat16_as_ushort(h1) << 16) |
                                      __bfloat16_as_ushort(h0);
                        uint32_t ll = ((uint32_t)__bfloat16_as_ushort(__float2bfloat16(l1)) << 16) |
                                      __bfloat16_as_ushort(__float2bfloat16(l0));
                        *reinterpret_cast<uint32_t*>(
                            reinterpret_cast<char*>(obh) + ((size_t)m * DIM + c) * 2) = hh;
                        *reinterpret_cast<uint32_t*>(
                            reinterpret_cast<char*>(obl) + ((size_t)m * DIM + c) * 2) = ll;
                    }
                }
            }
        }
    }
}

// ---------------- gather + edge ReLU + sum (bf16-split output) ----------------
__global__ __launch_bounds__(256)
void gather_sum_kernel(const float* __restrict__ A,
                       const float* __restrict__ B,
                       const void* __restrict__ idx_raw,
                       __nv_bfloat16* __restrict__ Hh,
                       __nv_bfloat16* __restrict__ Hl, int M)
{
    int node = blockIdx.x * 8 + (threadIdx.x >> 5);
    int lane = threadIdx.x & 31;
    if (node >= M) return;

    // int32 vs int64 index detection (int64 little-endian -> odd words all zero)
    const int* idx32 = (const int*)idx_raw;
    int w = idx32[(size_t)node * 32 + lane];
    unsigned zmask = __ballot_sync(0xffffffffu, w == 0);
    int j;
    if ((zmask & 0xAAAAAAAAu) == 0xAAAAAAAAu)
        j = (int)((const long long*)idx_raw)[(size_t)node * 32 + lane];
    else
        j = w;

    float4 a = reinterpret_cast<const float4*>(A + (size_t)node * DIM)[lane];
    float4 acc = make_float4(0.f, 0.f, 0.f, 0.f);
#pragma unroll
    for (int m = 0; m < 32; ++m) {
        int jm = __shfl_sync(0xffffffffu, j, m);
        float4 b = __ldg(reinterpret_cast<const float4*>(B + (size_t)jm * DIM) + lane);
        acc.x += fmaxf(a.x + b.x, 0.f);
        acc.y += fmaxf(a.y + b.y, 0.f);
        acc.z += fmaxf(a.z + b.z, 0.f);
        acc.w += fmaxf(a.w + b.w, 0.f);
    }
    float v[4] = {acc.x, acc.y, acc.z, acc.w};
    unsigned long long hh = 0, ll = 0;
#pragma unroll
    for (int e = 0; e < 4; ++e) {
        __nv_bfloat16 h = __float2bfloat16(v[e]);
        __nv_bfloat16 l = __float2bfloat16(v[e] - __bfloat162float(h));
        hh |= (unsigned long long)__bfloat16_as_ushort(h) << (16 * e);
        ll |= (unsigned long long)__bfloat16_as_ushort(l) << (16 * e);
    }
    reinterpret_cast<unsigned long long*>(Hh + (size_t)node * DIM)[lane] = hh;
    reinterpret_cast<unsigned long long*>(Hl + (size_t)node * DIM)[lane] = ll;
}

// ---------------- launch ----------------
extern "C" void kernel_launch(void* const* d_in, const int* in_sizes, int n_in,
                              void* d_out, int out_size)
{
    const float* X     = (const float*)d_in[0];
    const void*  idx   = d_in[2];
    const float* msgW1 = (const float*)d_in[3];
    const float* msgb1 = (const float*)d_in[4];
    const float* msgW2 = (const float*)d_in[5];
    const float* msgb2 = (const float*)d_in[6];
    const float* updW1 = (const float*)d_in[7];
    const float* updb1 = (const float*)d_in[8];
    const float* updW2 = (const float*)d_in[9];
    const float* updb2 = (const float*)d_in[10];
    float* out = (float*)d_out;

    float *A, *B;
    __nv_bfloat16 *Xh, *Xl, *Hh, *Hl, *aggh, *aggl, *uh, *ul;
    __nv_bfloat16 *w1h, *w1l, *w2h, *w2l, *u1h, *u1l, *u2h, *u2l;
    cudaGetSymbolAddress((void**)&A, g_A);       cudaGetSymbolAddress((void**)&B, g_B);
    cudaGetSymbolAddress((void**)&Xh, g_Xh);     cudaGetSymbolAddress((void**)&Xl, g_Xl);
    cudaGetSymbolAddress((void**)&Hh, g_Hh);     cudaGetSymbolAddress((void**)&Hl, g_Hl);
    cudaGetSymbolAddress((void**)&aggh, g_aggh); cudaGetSymbolAddress((void**)&aggl, g_aggl);
    cudaGetSymbolAddress((void**)&uh, g_uh);     cudaGetSymbolAddress((void**)&ul, g_ul);
    cudaGetSymbolAddress((void**)&w1h, g_w1h);   cudaGetSymbolAddress((void**)&w1l, g_w1l);
    cudaGetSymbolAddress((void**)&w2h, g_w2h);   cudaGetSymbolAddress((void**)&w2l, g_w2l);
    cudaGetSymbolAddress((void**)&u1h, g_u1h);   cudaGetSymbolAddress((void**)&u1l, g_u1l);
    cudaGetSymbolAddress((void**)&u2h, g_u2h);   cudaGetSymbolAddress((void**)&u2l, g_u2l);

    const int M = NATOMS;
    const int SMEM = 69632 + 2 * 36864;  // 143360 bytes
    cudaFuncSetAttribute(mma_kernel<0>, cudaFuncAttributeMaxDynamicSharedMemorySize, SMEM);
    cudaFuncSetAttribute(mma_kernel<1>, cudaFuncAttributeMaxDynamicSharedMemorySize, SMEM);
    cudaFuncSetAttribute(mma_kernel<2>, cudaFuncAttributeMaxDynamicSharedMemorySize, SMEM);
    cudaFuncSetAttribute(mma_kernel<3>, cudaFuncAttributeMaxDynamicSharedMemorySize, SMEM);

    // prep: bf16 splits of X and transposed+permuted weights
    conv_x_kernel<<<(M * DIM / 4 + 255) / 256, 256>>>(X, Xh, Xl, M * DIM / 4);
    conv_w_kernel<<<384, 256>>>(msgW1, msgW2, updW1, updW2,
                                w1h, w1l, w2h, w2l, u1h, u1l, u2h, u2l);

    // [A|B] = X @ [W1top|W1bot]; A gets +b1
    mma_kernel<0><<<MGRID, 256, SMEM>>>(Xh, Xl, nullptr, nullptr, w1h, w1l,
                                        msgb1, 1.f, nullptr, A, B, nullptr, nullptr, M);
    // H[i] = sum_j relu(A[i] + B[nbr[i][j]]) -> bf16 hi/lo
    gather_sum_kernel<<<(M + 7) / 8, 256>>>(A, B, idx, Hh, Hl, M);
    // agg = H @ msgW2 + 32*b2 -> bf16 hi/lo
    mma_kernel<1><<<MGRID, 256, SMEM>>>(Hh, Hl, nullptr, nullptr, w2h, w2l,
                                        msgb2, (float)MNBR, nullptr, nullptr, nullptr, aggh, aggl, M);
    // u = relu([X,agg] @ updW1 + b1) -> bf16 hi/lo
    mma_kernel<2><<<MGRID, 256, SMEM>>>(Xh, Xl, aggh, aggl, u1h, u1l,
                                        updb1, 1.f, nullptr, nullptr, nullptr, uh, ul, M);
    // out = relu(X + u @ updW2 + b2) -> f32
    mma_kernel<3><<<MGRID, 256, SMEM>>>(uh, ul, nullptr, nullptr, u2h, u2l,
                                        updb2, 1.f, X, out, nullptr, nullptr, nullptr, M);

    (void)in_sizes; (void)n_in; (void)out_size;
}

// round 5
// speedup vs baseline: 2.0977x; 1.2945x over previous
#include <cuda_runtime.h>
#include <cuda_bf16.h>
#include <cuda_fp16.h>
#include <cstdint>

#define NATOMS 25000
#define MNBR 32
#define DIM 128
#define MGRID 196            // ceil(25000/128)
#define TILE 34816           // 128 rows * 272B stride

// ---------------- scratch (device globals) ----------------
__device__ float g_A[(size_t)NATOMS * DIM];           // X@W1top + b1 (f32, gather self term)
__device__ __half g_B[(size_t)NATOMS * DIM];          // X@W1bot (fp16, gather bulk reads)
__device__ __nv_bfloat16 g_Hh[(size_t)NATOMS * DIM], g_Hl[(size_t)NATOMS * DIM];
// transposed bf16-split weights: Wt[n][k] plain row-major
__device__ __nv_bfloat16 g_w1h[256 * 128], g_w1l[256 * 128];   // [W1top^T | W1bot^T]
__device__ __nv_bfloat16 g_w2h[128 * 128], g_w2l[128 * 128];   // msgW2^T
__device__ __nv_bfloat16 g_u1h[128 * 256], g_u1l[128 * 256];   // updW1^T (N=128,K=256)
__device__ __nv_bfloat16 g_u2h[128 * 128], g_u2l[128 * 128];   // updW2^T

// ---------------- helpers ----------------
__device__ __forceinline__ uint32_t smem_u32(const void* p) {
    uint32_t a;
    asm("{ .reg .u64 t; cvta.to.shared.u64 t, %1; cvt.u32.u64 %0, t; }" : "=r"(a) : "l"(p));
    return a;
}
__device__ __forceinline__ void ldmat_x4(uint32_t* r, uint32_t a) {
    asm volatile("ldmatrix.sync.aligned.m8n8.x4.shared.b16 {%0,%1,%2,%3}, [%4];"
        : "=r"(r[0]), "=r"(r[1]), "=r"(r[2]), "=r"(r[3]) : "r"(a));
}
__device__ __forceinline__ void hmma(float* d, const uint32_t* a, uint2 b) {
    asm volatile("mma.sync.aligned.m16n8k16.row.col.f32.bf16.bf16.f32 "
        "{%0,%1,%2,%3}, {%4,%5,%6,%7}, {%8,%9}, {%0,%1,%2,%3};"
        : "+f"(d[0]), "+f"(d[1]), "+f"(d[2]), "+f"(d[3])
        : "r"(a[0]), "r"(a[1]), "r"(a[2]), "r"(a[3]), "r"(b.x), "r"(b.y));
}

// ---------------- weight transpose + bf16 split (plain, no permutation) ----------------
__global__ void conv_w_kernel(const float* __restrict__ msgW1,
                              const float* __restrict__ msgW2,
                              const float* __restrict__ updW1,
                              const float* __restrict__ updW2,
                              __nv_bfloat16* __restrict__ w1h, __nv_bfloat16* __restrict__ w1l,
                              __nv_bfloat16* __restrict__ w2h, __nv_bfloat16* __restrict__ w2l,
                              __nv_bfloat16* __restrict__ u1h, __nv_bfloat16* __restrict__ u1l,
                              __nv_bfloat16* __restrict__ u2h, __nv_bfloat16* __restrict__ u2l) {
    int idx = blockIdx.x * 256 + threadIdx.x;
    float v; __nv_bfloat16 *ph, *pl; int off;
    if (idx < 32768) {                       // w1: [256 n][128 k]
        int n = idx >> 7, k = idx & 127;
        v = (n < 128) ? msgW1[k * 128 + n] : msgW1[(128 + k) * 128 + (n - 128)];
        ph = w1h; pl = w1l; off = idx;
    } else if (idx < 49152) {                // w2: [128 n][128 k]
        int i = idx - 32768; int n = i >> 7, k = i & 127;
        v = msgW2[k * 128 + n]; ph = w2h; pl = w2l; off = i;
    } else if (idx < 81920) {                // u1: [128 n][256 k]
        int i = idx - 49152; int n = i >> 8, k = i & 255;
        v = updW1[k * 128 + n]; ph = u1h; pl = u1l; off = i;
    } else if (idx < 98304) {                // u2: [128 n][128 k]
        int i = idx - 81920; int n = i >> 7, k = i & 127;
        v = updW2[k * 128 + n]; ph = u2h; pl = u2l; off = i;
    } else return;
    __nv_bfloat16 h = __float2bfloat16(v);
    ph[off] = h;
    pl[off] = __float2bfloat16(v - __bfloat162float(h));
}

// ---------------- smem tile loaders (272B row stride, conflict-free ldmatrix) ----------------
__device__ __forceinline__ void load_bf16_tile(char* sm, int off,
                                               const __nv_bfloat16* __restrict__ src,
                                               int row0, int rowclamp, int stride, int k0) {
    int tid = threadIdx.x;
#pragma unroll
    for (int q = 0; q < 8; ++q) {
        int s = tid + q * 256;
        int r = s >> 4, c8 = (s & 15) << 3;
        int gr = row0 + r; if (gr > rowclamp) gr = rowclamp;
        uint4 v = *reinterpret_cast<const uint4*>(src + (size_t)gr * stride + k0 + c8);
        *reinterpret_cast<uint4*>(sm + off + r * 272 + (c8 << 1)) = v;
    }
}
// f32 -> bf16 hi/lo split, directly into two smem tiles
__device__ __forceinline__ void load_x_split(char* sm, int offh, int offl,
                                             const float* __restrict__ X, int m0, int M) {
    int tid = threadIdx.x;
#pragma unroll
    for (int q = 0; q < 16; ++q) {
        int s = tid + q * 256;
        int r = s >> 5, c4 = (s & 31) << 2;
        int gr = m0 + r; if (gr >= M) gr = M - 1;
        float4 f = *reinterpret_cast<const float4*>(X + (size_t)gr * DIM + c4);
        float v[4] = {f.x, f.y, f.z, f.w};
        unsigned long long ph = 0, pl = 0;
#pragma unroll
        for (int e = 0; e < 4; ++e) {
            __nv_bfloat16 h = __float2bfloat16(v[e]);
            __nv_bfloat16 l = __float2bfloat16(v[e] - __bfloat162float(h));
            ph |= (unsigned long long)__bfloat16_as_ushort(h) << (16 * e);
            pl |= (unsigned long long)__bfloat16_as_ushort(l) << (16 * e);
        }
        *reinterpret_cast<unsigned long long*>(sm + offh + r * 272 + (c4 << 1)) = ph;
        *reinterpret_cast<unsigned long long*>(sm + offl + r * 272 + (c4 << 1)) = pl;
    }
}

// ---------------- core 128x128x128 accumulate (3-product bf16 split) ----------------
__device__ __forceinline__ void gemm_tiles(uint32_t smb, int offAh, int offAl,
                                           int offWh, int offWl,
                                           int m0w, int n0w, int lane,
                                           float (&d)[2][8][4]) {
    for (int k0 = 0; k0 < 128; k0 += 16) {
        uint32_t ah[2][4], al[2][4];
#pragma unroll
        for (int i = 0; i < 2; ++i) {
            uint32_t ra = (uint32_t)((m0w + i * 16 + (lane & 15)) * 272 +
                                     ((k0 + ((lane >> 4) << 3)) << 1));
            ldmat_x4(ah[i], smb + offAh + ra);
            ldmat_x4(al[i], smb + offAl + ra);
        }
#pragma unroll
        for (int jj = 0; jj < 8; jj += 2) {
            // B fragment via ldmatrix.x4: mats = (n jj, k0), (n jj, k0+8), (n jj+1, k0), (n jj+1, k0+8)
            uint32_t rb = (uint32_t)((n0w + (jj + ((lane >> 4) & 1)) * 8 + (lane & 7)) * 272 +
                                     ((k0 + (((lane >> 3) & 1) << 3)) << 1));
            uint32_t bh[4], bl[4];
            ldmat_x4(bh, smb + offWh + rb);
            ldmat_x4(bl, smb + offWl + rb);
            uint2 bh0 = make_uint2(bh[0], bh[1]), bh1 = make_uint2(bh[2], bh[3]);
            uint2 bl0 = make_uint2(bl[0], bl[1]), bl1 = make_uint2(bl[2], bl[3]);
#pragma unroll
            for (int i = 0; i < 2; ++i) {
                hmma(d[i][jj], ah[i], bh0);
                hmma(d[i][jj], ah[i], bl0);
                hmma(d[i][jj], al[i], bh0);
                hmma(d[i][jj + 1], ah[i], bh1);
                hmma(d[i][jj + 1], ah[i], bl1);
                hmma(d[i][jj + 1], al[i], bh1);
            }
        }
    }
}
__device__ __forceinline__ void zero_d(float (&d)[2][8][4]) {
#pragma unroll
    for (int i = 0; i < 2; ++i)
#pragma unroll
        for (int j = 0; j < 8; ++j)
#pragma unroll
            for (int e = 0; e < 4; ++e) d[i][j][e] = 0.f;
}
// write register tile into smem as bf16 hi/lo split (bias + optional relu)
template<bool RELU>
__device__ __forceinline__ void store_smem_split(char* sm, int offH, int offL,
        float (&d)[2][8][4], const float* __restrict__ bias, float bscale,
        int m0w, int n0w, int lane) {
    int g = lane >> 2, tg = lane & 3;
#pragma unroll
    for (int j = 0; j < 8; ++j) {
        int c = n0w + j * 8 + 2 * tg;
        float b0 = bscale * __ldg(bias + c), b1 = bscale * __ldg(bias + c + 1);
#pragma unroll
        for (int i = 0; i < 2; ++i)
#pragma unroll
            for (int h = 0; h < 2; ++h) {
                int r = m0w + i * 16 + g + h * 8;
                float v0 = d[i][j][2 * h] + b0, v1 = d[i][j][2 * h + 1] + b1;
                if (RELU) { v0 = fmaxf(v0, 0.f); v1 = fmaxf(v1, 0.f); }
                __nv_bfloat16 h0 = __float2bfloat16(v0), h1 = __float2bfloat16(v1);
                float l0 = v0 - __bfloat162float(h0), l1 = v1 - __bfloat162float(h1);
                uint32_t hh = ((uint32_t)__bfloat16_as_ushort(h1) << 16) |
                              __bfloat16_as_ushort(h0);
                uint32_t ll = ((uint32_t)__bfloat16_as_ushort(__float2bfloat16(l1)) << 16) |
                              __bfloat16_as_ushort(__float2bfloat16(l0));
                *reinterpret_cast<uint32_t*>(sm + offH + r * 272 + c * 2) = hh;
                *reinterpret_cast<uint32_t*>(sm + offL + r * 272 + c * 2) = ll;
            }
    }
}

// ---------------- head kernel: [A|B] = X @ [W1top|W1bot]; A += b1 (f32), B -> fp16 ----------------
__global__ __launch_bounds__(256, 1)
void head_kernel(const float* __restrict__ X,
                 const __nv_bfloat16* __restrict__ w1h, const __nv_bfloat16* __restrict__ w1l,
                 const float* __restrict__ msgb1,
                 float* __restrict__ outA, __half* __restrict__ outB, int M)
{
    constexpr int S0 = 0, S1 = TILE, WB = 2 * TILE;
    extern __shared__ char smem[];
    const uint32_t smb = smem_u32(smem);
    const int tid = threadIdx.x, wid = tid >> 5, lane = tid & 31;
    const int g = lane >> 2, tg = lane & 3;
    const int m0 = blockIdx.x * 128;
    const int m0w = (wid & 3) * 32, n0w = (wid >> 2) * 64;

    load_x_split(smem, S0, S1, X, m0, M);
#pragma unroll
    for (int p = 0; p < 2; ++p) {
        load_bf16_tile(smem, WB + (2 * p) * TILE,     w1h, p * 128, p * 128 + 127, 128, 0);
        load_bf16_tile(smem, WB + (2 * p + 1) * TILE, w1l, p * 128, p * 128 + 127, 128, 0);
    }
    __syncthreads();

#pragma unroll
    for (int p = 0; p < 2; ++p) {
        float d[2][8][4];
        zero_d(d);
        gemm_tiles(smb, S0, S1, WB + 2 * p * TILE, WB + (2 * p + 1) * TILE, m0w, n0w, lane, d);
#pragma unroll
        for (int j = 0; j < 8; ++j) {
            int c = n0w + j * 8 + 2 * tg;
            float b0 = 0.f, b1 = 0.f;
            if (p == 0) { b0 = __ldg(msgb1 + c); b1 = __ldg(msgb1 + c + 1); }
#pragma unroll
            for (int i = 0; i < 2; ++i)
#pragma unroll
                for (int h = 0; h < 2; ++h) {
                    int m = m0 + m0w + i * 16 + g + h * 8;
                    if (m >= M) continue;
                    float v0 = d[i][j][2 * h] + b0, v1 = d[i][j][2 * h + 1] + b1;
                    if (p == 0) {
                        *reinterpret_cast<float2*>(outA + (size_t)m * DIM + c) =
                            make_float2(v0, v1);
                    } else {
                        *reinterpret_cast<__half2*>(outB + (size_t)m * DIM + c) =
                            __floats2half2_rn(v0, v1);
                    }
                }
        }
    }
}

// ---------------- fused tail: agg -> u -> out, all row-local ----------------
__global__ __launch_bounds__(256, 1)
void fused_tail_kernel(const __nv_bfloat16* __restrict__ Hh, const __nv_bfloat16* __restrict__ Hl,
                       const float* __restrict__ X,
                       const __nv_bfloat16* __restrict__ w2h, const __nv_bfloat16* __restrict__ w2l,
                       const __nv_bfloat16* __restrict__ u1h, const __nv_bfloat16* __restrict__ u1l,
                       const __nv_bfloat16* __restrict__ u2h, const __nv_bfloat16* __restrict__ u2l,
                       const float* __restrict__ msgb2, const float* __restrict__ updb1,
                       const float* __restrict__ updb2,
                       float* __restrict__ out, int M)
{
    constexpr int S0 = 0, S1 = TILE, S2 = 2 * TILE, S3 = 3 * TILE, W0 = 4 * TILE, W1 = 5 * TILE;
    extern __shared__ char smem[];
    const uint32_t smb = smem_u32(smem);
    const int tid = threadIdx.x, wid = tid >> 5, lane = tid & 31;
    const int g = lane >> 2, tg = lane & 3;
    const int m0 = blockIdx.x * 128;
    const int m0w = (wid & 3) * 32, n0w = (wid >> 2) * 64;

    // stage 1 inputs: H (A), X (for stage2), w2 (W)
    load_bf16_tile(smem, S0, Hh, m0, M - 1, 128, 0);
    load_bf16_tile(smem, S1, Hl, m0, M - 1, 128, 0);
    load_x_split(smem, S2, S3, X, m0, M);
    load_bf16_tile(smem, W0, w2h, 0, 127, 128, 0);
    load_bf16_tile(smem, W1, w2l, 0, 127, 128, 0);
    __syncthreads();

    float d[2][8][4];
    // ---- stage 1: agg = H @ w2 + 32*b2 ----
    zero_d(d);
    gemm_tiles(smb, S0, S1, W0, W1, m0w, n0w, lane, d);
    __syncthreads();                                  // all H/W reads done
    store_smem_split<false>(smem, S0, S1, d, msgb2, (float)MNBR, m0w, n0w, lane);  // agg -> S0/S1
    load_bf16_tile(smem, W0, u1h, 0, 127, 256, 0);    // u1 k[0:128]
    load_bf16_tile(smem, W1, u1l, 0, 127, 256, 0);
    __syncthreads();

    // ---- stage 2: u = relu(X @ u1[:, :128] + agg @ u1[:, 128:] + b1) ----
    zero_d(d);
    gemm_tiles(smb, S2, S3, W0, W1, m0w, n0w, lane, d);   // X part
    __syncthreads();                                  // W reads done
    load_bf16_tile(smem, W0, u1h, 0, 127, 256, 128);  // u1 k[128:256]
    load_bf16_tile(smem, W1, u1l, 0, 127, 256, 128);
    __syncthreads();
    gemm_tiles(smb, S0, S1, W0, W1, m0w, n0w, lane, d);   // agg part (accumulate)
    __syncthreads();                                  // agg/W reads done
    store_smem_split<true>(smem, S0, S1, d, updb1, 1.f, m0w, n0w, lane);  // u -> S0/S1
    load_bf16_tile(smem, W0, u2h, 0, 127, 128, 0);
    load_bf16_tile(smem, W1, u2l, 0, 127, 128, 0);
    __syncthreads();

    // ---- stage 3: out = relu(X + u @ u2 + b2) ----
    zero_d(d);
    gemm_tiles(smb, S0, S1, W0, W1, m0w, n0w, lane, d);
#pragma unroll
    for (int j = 0; j < 8; ++j) {
        int c = n0w + j * 8 + 2 * tg;
        float b0 = __ldg(updb2 + c), b1 = __ldg(updb2 + c + 1);
#pragma unroll
        for (int i = 0; i < 2; ++i)
#pragma unroll
            for (int h = 0; h < 2; ++h) {
                int m = m0 + m0w + i * 16 + g + h * 8;
                if (m >= M) continue;
                float2 rx = *reinterpret_cast<const float2*>(X + (size_t)m * DIM + c);
                float v0 = fmaxf(d[i][j][2 * h] + b0 + rx.x, 0.f);
                float v1 = fmaxf(d[i][j][2 * h + 1] + b1 + rx.y, 0.f);
                *reinterpret_cast<float2*>(out + (size_t)m * DIM + c) = make_float2(v0, v1);
            }
    }
}

// ---------------- gather + edge ReLU + sum (fp16 B reads, f32 math, bf16-split out) ----------------
__global__ __launch_bounds__(256)
void gather_sum_kernel(const float* __restrict__ A,
                       const __half* __restrict__ B,
                       const void* __restrict__ idx_raw,
                       __nv_bfloat16* __restrict__ Hh,
                       __nv_bfloat16* __restrict__ Hl, int M)
{
    int node = blockIdx.x * 8 + (threadIdx.x >> 5);
    int lane = threadIdx.x & 31;
    if (node >= M) return;

    // int32 vs int64 index detection (int64 little-endian -> odd words all zero)
    const int* idx32 = (const int*)idx_raw;
    int w = idx32[(size_t)node * 32 + lane];
    unsigned zmask = __ballot_sync(0xffffffffu, w == 0);
    int j;
    if ((zmask & 0xAAAAAAAAu) == 0xAAAAAAAAu)
        j = (int)((const long long*)idx_raw)[(size_t)node * 32 + lane];
    else
        j = w;

    float4 a = reinterpret_cast<const float4*>(A + (size_t)node * DIM)[lane];
    float4 acc = make_float4(0.f, 0.f, 0.f, 0.f);
#pragma unroll
    for (int m = 0; m < 32; ++m) {
        int jm = __shfl_sync(0xffffffffu, j, m);
        uint2 raw = __ldg(reinterpret_cast<const uint2*>(B + (size_t)jm * DIM) + lane);
        float2 f01 = __half22float2(*reinterpret_cast<__half2*>(&raw.x));
        float2 f23 = __half22float2(*reinterpret_cast<__half2*>(&raw.y));
        acc.x += fmaxf(a.x + f01.x, 0.f);
        acc.y += fmaxf(a.y + f01.y, 0.f);
        acc.z += fmaxf(a.z + f23.x, 0.f);
        acc.w += fmaxf(a.w + f23.y, 0.f);
    }
    float v[4] = {acc.x, acc.y, acc.z, acc.w};
    unsigned long long hh = 0, ll = 0;
#pragma unroll
    for (int e = 0; e < 4; ++e) {
        __nv_bfloat16 h = __float2bfloat16(v[e]);
        __nv_bfloat16 l = __float2bfloat16(v[e] - __bfloat162float(h));
        hh |= (unsigned long long)__bfloat16_as_ushort(h) << (16 * e);
        ll |= (unsigned long long)__bfloat16_as_ushort(l) << (16 * e);
    }
    reinterpret_cast<unsigned long long*>(Hh + (size_t)node * DIM)[lane] = hh;
    reinterpret_cast<unsigned long long*>(Hl + (size_t)node * DIM)[lane] = ll;
}

// ---------------- launch ----------------
extern "C" void kernel_launch(void* const* d_in, const int* in_sizes, int n_in,
                              void* d_out, int out_size)
{
    const float* X     = (const float*)d_in[0];
    const void*  idx   = d_in[2];
    const float* msgW1 = (const float*)d_in[3];
    const float* msgb1 = (const float*)d_in[4];
    const float* msgW2 = (const float*)d_in[5];
    const float* msgb2 = (const float*)d_in[6];
    const float* updW1 = (const float*)d_in[7];
    const float* updb1 = (const float*)d_in[8];
    const float* updW2 = (const float*)d_in[9];
    const float* updb2 = (const float*)d_in[10];
    float* out = (float*)d_out;

    float* A; __half* B;
    __nv_bfloat16 *Hh, *Hl;
    __nv_bfloat16 *w1h, *w1l, *w2h, *w2l, *u1h, *u1l, *u2h, *u2l;
    cudaGetSymbolAddress((void**)&A, g_A);       cudaGetSymbolAddress((void**)&B, g_B);
    cudaGetSymbolAddress((void**)&Hh, g_Hh);     cudaGetSymbolAddress((void**)&Hl, g_Hl);
    cudaGetSymbolAddress((void**)&w1h, g_w1h);   cudaGetSymbolAddress((void**)&w1l, g_w1l);
    cudaGetSymbolAddress((void**)&w2h, g_w2h);   cudaGetSymbolAddress((void**)&w2l, g_w2l);
    cudaGetSymbolAddress((void**)&u1h, g_u1h);   cudaGetSymbolAddress((void**)&u1l, g_u1l);
    cudaGetSymbolAddress((void**)&u2h, g_u2h);   cudaGetSymbolAddress((void**)&u2l, g_u2l);

    const int M = NATOMS;
    const int SMEM = 6 * TILE;   // 208896 bytes
    cudaFuncSetAttribute(head_kernel, cudaFuncAttributeMaxDynamicSharedMemorySize, SMEM);
    cudaFuncSetAttribute(fused_tail_kernel, cudaFuncAttributeMaxDynamicSharedMemorySize, SMEM);

    conv_w_kernel<<<384, 256>>>(msgW1, msgW2, updW1, updW2,
                                w1h, w1l, w2h, w2l, u1h, u1l, u2h, u2l);
    head_kernel<<<MGRID, 256, SMEM>>>(X, w1h, w1l, msgb1, A, B, M);
    gather_sum_kernel<<<(M + 7) / 8, 256>>>(A, B, idx, Hh, Hl, M);
    fused_tail_kernel<<<MGRID, 256, SMEM>>>(Hh, Hl, X, w2h, w2l, u1h, u1l, u2h, u2l,
                                            msgb2, updb1, updb2, out, M);

    (void)in_sizes; (void)n_in; (void)out_size;
}